// round 11
// baseline (speedup 1.0000x reference)
#include <cuda_runtime.h>
#include <math.h>
#include <stdint.h>

#define CIN   16
#define OC    64
#define NPIX  7200          // 8*30*30
#define KDIM  144
#define NTOT  72            // 64 oc + ones col + 7 pad
#define ASTR  148           // A row stride in floats (bank-conflict-free fragments)
#define MT    64            // M rows per block
#define NBLK  113           // ceil(7200/64)

// dynamic smem: [koff 64f][xsum 64f][sdw 1f][pad][A 64*148 u32][B 18*9*64 u32]
#define A_OFF_BYTES 1024
#define A_U32       (MT * ASTR)             // 9472
#define B_U32       (18 * 9 * 64)           // 10368
#define SMEM_BYTES  (A_OFF_BYTES + A_U32 * 4 + B_U32 * 4)   // 80384

__device__ __forceinline__ uint32_t f2tf(float f) {
    uint32_t u;
    asm("cvt.rna.tf32.f32 %0, %1;" : "=r"(u) : "f"(f));
    return u;
}

__device__ __forceinline__ void mma_tf32(float* d, const uint32_t* a, const uint32_t* b) {
    asm volatile(
        "mma.sync.aligned.m16n8k8.row.col.f32.tf32.tf32.f32 "
        "{%0,%1,%2,%3}, {%4,%5,%6,%7}, {%8,%9}, {%0,%1,%2,%3};"
        : "+f"(d[0]), "+f"(d[1]), "+f"(d[2]), "+f"(d[3])
        : "r"(a[0]), "r"(a[1]), "r"(a[2]), "r"(a[3]), "r"(b[0]), "r"(b[1]));
}

template<int NT0, int NTN>
__device__ __forceinline__ void mma_loop(float acc[5][4],
                                         const uint32_t* __restrict__ Arow,
                                         const uint32_t* __restrict__ smB,
                                         int lane) {
    #pragma unroll
    for (int ks = 0; ks < 18; ks++) {
        uint32_t a[4];
        a[0] = Arow[ks * 8];
        a[1] = Arow[ks * 8 + 8 * ASTR];
        a[2] = Arow[ks * 8 + 4];
        a[3] = Arow[ks * 8 + 4 + 8 * ASTR];
        #pragma unroll
        for (int j = 0; j < NTN; j++) {
            const uint2 bv = *(const uint2*)(smB + (ks * 9 + NT0 + j) * 64 + lane * 2);
            uint32_t b[2] = {bv.x, bv.y};
            mma_tf32(acc[j], a, b);
        }
    }
}

__global__ __launch_bounds__(256, 1)
void conv_mma_kernel(const float* __restrict__ x,
                     const float* __restrict__ kw_,
                     const float* __restrict__ bias,
                     const float* __restrict__ dxp,
                     const float* __restrict__ dwp,
                     float* __restrict__ out) {
    extern __shared__ char sm[];
    float*    koff_s = (float*)sm;              // 64
    float*    xsum_s = koff_s + 64;             // 64
    float*    sdw_s  = xsum_s + 64;             // 1
    uint32_t* smA    = (uint32_t*)(sm + A_OFF_BYTES);
    uint32_t* smB    = smA + A_U32;

    const int t    = threadIdx.x;
    const int lane = t & 31;
    const int wid  = t >> 5;

    // ---- Stage A: im2col of tf32(clamp(x+5)); 4 threads/row, 36 kf each ----
    {
        const int m   = t >> 2;
        const int kf0 = (t & 3) * 36;
        const int p   = blockIdx.x * MT + m;
        uint32_t* arow = smA + m * ASTR;
        if (p < NPIX) {
            const int img = p / 900, rem = p % 900, i = rem / 30, jj = rem % 30;
            const float* xb = x + (size_t)img * CIN * 1024 + i * 32 + jj;
            #pragma unroll 12
            for (int kf = kf0; kf < kf0 + 36; kf++) {
                const int pos = kf >> 4, c = kf & 15;
                const int kh = pos / 3, kw = pos % 3;
                const float v = fmaxf(xb[c * 1024 + kh * 32 + kw] + 5.0f, 1e-12f);
                arow[kf] = f2tf(v);
            }
        } else {
            #pragma unroll 12
            for (int kf = kf0; kf < kf0 + 36; kf++)
                arow[kf] = 0u;
        }
    }

    // ---- Stage B in fragment-major order: exp(k+5), ones col 64, zero pad ----
    for (int idx = t; idx < KDIM * NTOT; idx += 256) {
        const int kf = idx / NTOT;
        const int n  = idx - kf * NTOT;
        float v;
        if (n < OC)       v = expf(kw_[kf * OC + n] + 5.0f);
        else              v = (n == OC) ? 1.0f : 0.0f;
        const int ks = kf >> 3, nt = n >> 3;
        const int ln = (n & 7) * 4 + (kf & 3);
        const int rg = (kf >> 2) & 1;
        smB[(ks * 9 + nt) * 64 + ln * 2 + rg] = f2tf(v);
    }

    // ---- koff + sdw ----
    if (t < OC) {
        float s = 0.0f;
        #pragma unroll 8
        for (int r = 0; r < KDIM; r++) s += kw_[r * OC + t];
        koff_s[t] = bias[t] - dxp[0] * s;
    }
    if (t == 0) sdw_s[0] = dwp[0];
    __syncthreads();

    // ---- MMA mainloop: warp = (mtile wm, ngroup wn) ----
    const int wm  = wid & 3;      // m-tile: rows wm*16 .. +15
    const int wn  = wid >> 2;     // 0: ntiles 0-4, 1: ntiles 5-8
    const int gr  = lane >> 2;
    const int tig = lane & 3;

    float acc[5][4];
    #pragma unroll
    for (int j = 0; j < 5; j++)
        #pragma unroll
        for (int q = 0; q < 4; q++) acc[j][q] = 0.0f;

    const uint32_t* Arow = smA + (wm * 16 + gr) * ASTR + tig;
    if (wn == 0) mma_loop<0, 5>(acc, Arow, smB, lane);
    else         mma_loop<5, 4>(acc, Arow, smB, lane);

    // ---- xsum broadcast: ones column (global col 64 = tile 8, local col 0) ----
    if (wn == 1 && tig == 0) {
        xsum_s[wm * 16 + gr]     = acc[3][0];
        xsum_s[wm * 16 + gr + 8] = acc[3][2];
    }
    __syncthreads();

    // ---- Epilogue: D - dw*(xsum-720) + koff ----
    const int NTout = wn ? 3 : 5;    // wn=1 skips the ones/pad tile
    const int r1 = wm * 16 + gr;
    const int p1 = blockIdx.x * MT + r1;
    const float sdw = sdw_s[0];
    #pragma unroll
    for (int h = 0; h < 2; h++) {
        const int r = r1 + h * 8, p = p1 + h * 8;
        if (p < NPIX) {
            const int img = p / 900, rem = p % 900, i = rem / 30, jj = rem % 30;
            const float corr = sdw * (xsum_s[r] - 720.0f);
            float* ob = out + (size_t)img * OC * 900 + i * 30 + jj;
            for (int j = 0; j < NTout; j++) {
                const int cb = (wn * 5 + j) * 8 + 2 * tig;
                ob[(size_t)cb * 900]       = acc[j][h * 2]     - corr + koff_s[cb];
                ob[(size_t)(cb + 1) * 900] = acc[j][h * 2 + 1] - corr + koff_s[cb + 1];
            }
        }
    }
}

extern "C" void kernel_launch(void* const* d_in, const int* in_sizes, int n_in,
                              void* d_out, int out_size) {
    const float* x    = (const float*)d_in[0];
    const float* k    = (const float*)d_in[1];
    const float* bias = (const float*)d_in[2];
    const float* dx   = (const float*)d_in[3];
    const float* dw   = (const float*)d_in[4];
    float* out = (float*)d_out;

    cudaFuncSetAttribute(conv_mma_kernel,
                         cudaFuncAttributeMaxDynamicSharedMemorySize, SMEM_BYTES);
    conv_mma_kernel<<<NBLK, 256, SMEM_BYTES>>>(x, k, bias, dx, dw, out);
}

// round 12
// speedup vs baseline: 1.1633x; 1.1633x over previous
#include <cuda_runtime.h>
#include <math.h>
#include <stdint.h>

#define CIN   16
#define OC    64
#define NPIX  7200          // 8*30*30
#define KDIM  144
#define ASTR  148           // A row stride (u32) -> conflict-free MMA fragment LDS
#define MT    64            // M rows per block
#define NBLK  113           // ceil(7200/64)

// smem layout (bytes): koff@0(256) xsum@256(256) sdw@512 part@768(2048) A@3072 B@40960
#define KOFF_OFF 0
#define XSUM_OFF 256
#define SDW_OFF  512
#define PART_OFF 768
#define A_OFF    3072
#define B_OFF    (A_OFF + MT*ASTR*4)        // 3072+37888 = 40960
#define SMEM_BYTES (B_OFF + 18*9*64*4)      // +41472 = 82432

__device__ __forceinline__ uint32_t f2tf(float f) {
    uint32_t u;
    asm("cvt.rna.tf32.f32 %0, %1;" : "=r"(u) : "f"(f));
    return u;
}

__device__ __forceinline__ void mma_tf32(float* d, const uint32_t* a, const uint32_t* b) {
    asm volatile(
        "mma.sync.aligned.m16n8k8.row.col.f32.tf32.tf32.f32 "
        "{%0,%1,%2,%3}, {%4,%5,%6,%7}, {%8,%9}, {%0,%1,%2,%3};"
        : "+f"(d[0]), "+f"(d[1]), "+f"(d[2]), "+f"(d[3])
        : "r"(a[0]), "r"(a[1]), "r"(a[2]), "r"(a[3]), "r"(b[0]), "r"(b[1]));
}

template<int NT0, int NTN>
__device__ __forceinline__ void mma_loop(float (&acc)[3][4],
                                         const uint32_t* __restrict__ Arow,
                                         const uint32_t* __restrict__ smB,
                                         int lane) {
    #pragma unroll
    for (int ks = 0; ks < 18; ks++) {
        uint32_t a[4];
        a[0] = Arow[ks * 8];
        a[1] = Arow[ks * 8 + 8 * ASTR];
        a[2] = Arow[ks * 8 + 4];
        a[3] = Arow[ks * 8 + 4 + 8 * ASTR];
        #pragma unroll
        for (int j = 0; j < NTN; j++) {
            const uint2 bv = *(const uint2*)(smB + (ks * 9 + NT0 + j) * 64 + lane * 2);
            uint32_t b[2] = {bv.x, bv.y};
            mma_tf32(acc[j], a, b);
        }
    }
}

__global__ __launch_bounds__(512, 1)
void conv_mma_kernel(const float* __restrict__ x,
                     const float* __restrict__ kw_,
                     const float* __restrict__ bias,
                     const float* __restrict__ dxp,
                     const float* __restrict__ dwp,
                     float* __restrict__ out) {
    extern __shared__ char sm[];
    float*    koff_s = (float*)(sm + KOFF_OFF);
    float*    xsum_s = (float*)(sm + XSUM_OFF);
    float*    sdw_s  = (float*)(sm + SDW_OFF);
    float*    part   = (float*)(sm + PART_OFF);   // [8][64]
    uint32_t* smA    = (uint32_t*)(sm + A_OFF);
    uint32_t* smB    = (uint32_t*)(sm + B_OFF);

    const int t    = threadIdx.x;
    const int lane = t & 31;
    const int wid  = t >> 5;

    // ---- Stage A: im2col tf32(clamp(x+5)); thread = (row, c-octet); all offsets immediate ----
    {
        const int m = t >> 3;          // 0..63
        const int s = t & 7;           // c and c+8
        const int p = blockIdx.x * MT + m;
        uint32_t* ar0 = smA + m * ASTR + s;
        uint32_t* ar1 = ar0 + 8;
        if (p < NPIX) {
            const int img = p / 900, rem = p % 900, i = rem / 30, jj = rem % 30;
            const float* xb0 = x + (size_t)img * 16384 + s * 1024 + i * 32 + jj;
            const float* xb1 = xb0 + 8 * 1024;
            #pragma unroll
            for (int pos = 0; pos < 9; pos++) {
                const int go = (pos / 3) * 32 + (pos % 3);   // compile-time
                ar0[pos * 16] = f2tf(fmaxf(xb0[go] + 5.0f, 1e-12f));
                ar1[pos * 16] = f2tf(fmaxf(xb1[go] + 5.0f, 1e-12f));
            }
        } else {
            #pragma unroll
            for (int pos = 0; pos < 9; pos++) {
                ar0[pos * 16] = 0u;
                ar1[pos * 16] = 0u;
            }
        }
    }

    // ---- Stage B: fragment-major tf32(exp(k+5)); lane varies kf -> conflict-free STS;
    //      the 18 loaded k values double as koff partial sums ----
    {
        const int kfl = t & 7;             // kf low bits
        const int n0  = (t >> 3) & 63;     // n
        const int nt  = n0 >> 3;
        const int ln  = (n0 & 7) * 4 + (kfl & 3);
        const int rg  = (kfl >> 2) & 1;
        uint32_t* bb = smB + nt * 64 + ln * 2 + rg;
        const float* kcol = kw_ + kfl * OC + n0;
        float psum = 0.0f;
        #pragma unroll
        for (int u = 0; u < 18; u++) {     // kf = u*8 + kfl, ks = u
            const float kv = kcol[u * 8 * OC];
            psum += kv;
            bb[u * 9 * 64] = f2tf(expf(kv + 5.0f));
        }
        part[kfl * 64 + n0] = psum;
    }
    // ---- Ones/pad tile (nt = 8): e<8 are the ones-column slots ----
    for (int idx = t; idx < 18 * 64; idx += 512) {
        const int ks = idx >> 6, e = idx & 63;
        smB[(ks * 9 + 8) * 64 + e] = (e < 8) ? 0x3f800000u : 0u;
    }
    if (t == 0) sdw_s[0] = dwp[0];
    __syncthreads();

    if (t < OC) {
        float s = 0.0f;
        #pragma unroll
        for (int q = 0; q < 8; q++) s += part[q * 64 + t];
        koff_s[t] = bias[t] - dxp[0] * s;
    }

    // ---- MMA: warp = (m-tile wm, n-group wn); groups {0-2},{3-4},{5-6},{7-8} ----
    const int wm  = wid & 3;
    const int wn  = wid >> 2;
    const int gr  = lane >> 2;
    const int tig = lane & 3;

    float acc[3][4];
    #pragma unroll
    for (int j = 0; j < 3; j++)
        #pragma unroll
        for (int q = 0; q < 4; q++) acc[j][q] = 0.0f;

    const uint32_t* Arow = smA + (wm * 16 + gr) * ASTR + tig;
    if      (wn == 0) mma_loop<0, 3>(acc, Arow, smB, lane);
    else if (wn == 1) mma_loop<3, 2>(acc, Arow, smB, lane);
    else if (wn == 2) mma_loop<5, 2>(acc, Arow, smB, lane);
    else              mma_loop<7, 2>(acc, Arow, smB, lane);

    // ---- xsum from ones column (tile 8 = group 3 j=1, local col 0) ----
    if (wn == 3 && tig == 0) {
        xsum_s[wm * 16 + gr]     = acc[1][0];
        xsum_s[wm * 16 + gr + 8] = acc[1][2];
    }
    __syncthreads();

    // ---- Epilogue ----
    const int NTout  = (wn == 0) ? 3 : ((wn == 3) ? 1 : 2);
    const int ntbase = (wn == 0) ? 0 : (2 * wn + 1);
    const int r1 = wm * 16 + gr;
    const int p1 = blockIdx.x * MT + r1;
    const float sdw = sdw_s[0];
    #pragma unroll
    for (int h = 0; h < 2; h++) {
        const int p = p1 + h * 8;
        if (p < NPIX) {
            const int img = p / 900, rem = p % 900, i = rem / 30, jj = rem % 30;
            const float corr = sdw * (xsum_s[r1 + h * 8] - 720.0f);
            float* ob = out + (size_t)img * OC * 900 + i * 30 + jj;
            for (int j = 0; j < NTout; j++) {
                const int cb = (ntbase + j) * 8 + 2 * tig;
                ob[(size_t)cb * 900]       = acc[j][h * 2]     - corr + koff_s[cb];
                ob[(size_t)(cb + 1) * 900] = acc[j][h * 2 + 1] - corr + koff_s[cb + 1];
            }
        }
    }
}

extern "C" void kernel_launch(void* const* d_in, const int* in_sizes, int n_in,
                              void* d_out, int out_size) {
    const float* x    = (const float*)d_in[0];
    const float* k    = (const float*)d_in[1];
    const float* bias = (const float*)d_in[2];
    const float* dx   = (const float*)d_in[3];
    const float* dw   = (const float*)d_in[4];
    float* out = (float*)d_out;

    cudaFuncSetAttribute(conv_mma_kernel,
                         cudaFuncAttributeMaxDynamicSharedMemorySize, SMEM_BYTES);
    conv_mma_kernel<<<NBLK, 512, SMEM_BYTES>>>(x, k, bias, dx, dw, out);
}